// round 4
// baseline (speedup 1.0000x reference)
#include <cuda_runtime.h>
#include <math.h>

// Problem constants
#define NB   64        // batch
#define NT   256       // seq len
#define NBT  16384     // NB*NT
#define NTC  16        // char seq len
#define NCE  25        // char embed
#define NCH  25        // char hidden
#define NWE  100       // word embed
#define NWH  100       // word hidden
#define NDW  150       // word-LSTM input dim
#define NL   25        // labels

typedef unsigned long long u64;

// Scratch (device globals; no allocations allowed)
__device__ float g_char_feat[NBT * 50];
__device__ float g_x[NBT * NDW];
__device__ float g_xw_f[NBT * 400];
__device__ float g_xw_b[NBT * 400];
__device__ float g_seq[NBT * 200];
__device__ float g_em[NBT * NL];
__device__ float g_crf[NB];

// Accurate activations: recurrences amplify per-step error over 256 steps,
// and these run on a small minority of lanes, so accuracy is ~free.
__device__ __forceinline__ float sigm(float x) { return 1.f / (1.f + expf(-x)); }
__device__ __forceinline__ float tanh_f(float x) { return tanhf(x); }

// ---- packed fp32x2 helpers (sm_103a): two EXACT fp32 FMAs per instruction ----
__device__ __forceinline__ u64 pack2(float lo, float hi) {
    u64 r; asm("mov.b64 %0, {%1, %2};" : "=l"(r) : "f"(lo), "f"(hi)); return r;
}
__device__ __forceinline__ void unpack2(u64 v, float& lo, float& hi) {
    asm("mov.b64 {%0, %1}, %2;" : "=f"(lo), "=f"(hi) : "l"(v));
}
__device__ __forceinline__ void ffma2(u64& d, u64 a, u64 b) {
    asm("fma.rn.f32x2 %0, %1, %2, %0;" : "+l"(d) : "l"(a), "l"(b));
}

// ---------------------------------------------------------------------------
// K1: char BiLSTM. One block per word; threads 0-127 = fwd gates, 128-255 = bwd.
// Each thread holds one gate's Wih/Whh columns in registers. Runs only `len`
// steps (hidden at index len-1 depends only on the first len inputs).
// ---------------------------------------------------------------------------
__global__ void char_lstm_kernel(const int* __restrict__ char_tensor,
                                 const int* __restrict__ char_lengths,
                                 const float* __restrict__ char_emb,
                                 const float* __restrict__ wih_f, const float* __restrict__ whh_f,
                                 const float* __restrict__ b_f,
                                 const float* __restrict__ wih_b, const float* __restrict__ whh_b,
                                 const float* __restrict__ b_b)
{
    int word = blockIdx.x;
    int tid = threadIdx.x;
    int dir = tid >> 7;       // 0 fwd, 1 bwd
    int g = tid & 127;        // gate id (valid < 100)

    __shared__ float ce_s[NTC][NCE];
    __shared__ int cidx[NTC];
    __shared__ float h_s[2][NCH];
    __shared__ float gate_s[2][100];

    int len = char_lengths[word];
    if (tid < NTC) cidx[tid] = char_tensor[word * NTC + tid];
    __syncthreads();
    for (int e = tid; e < NTC * NCE; e += 256) {
        int t = e / NCE, k = e % NCE;
        ce_s[t][k] = char_emb[cidx[t] * NCE + k];
    }

    float wih_r[NCE], whh_r[NCH], br = 0.f;
    if (g < 100) {
        const float* wih = dir ? wih_b : wih_f;
        const float* whh = dir ? whh_b : whh_f;
        br = (dir ? b_b : b_f)[g];
#pragma unroll
        for (int k = 0; k < NCE; k++) wih_r[k] = wih[k * 100 + g];
#pragma unroll
        for (int k = 0; k < NCH; k++) whh_r[k] = whh[k * 100 + g];
    }

    float c = 0.f;
    if (g < NCH) h_s[dir][g] = 0.f;
    __syncthreads();

    for (int t = 0; t < len; t++) {
        int xt = dir ? (len - 1 - t) : t;
        if (g < 100) {
            // 4 independent FMA chains to cut dependency latency
            float a0 = br, a1 = 0.f, a2 = 0.f, a3 = 0.f;
#pragma unroll
            for (int k = 0; k < 24; k += 4) {
                a0 += ce_s[xt][k + 0] * wih_r[k + 0];
                a1 += ce_s[xt][k + 1] * wih_r[k + 1];
                a2 += ce_s[xt][k + 2] * wih_r[k + 2];
                a3 += ce_s[xt][k + 3] * wih_r[k + 3];
            }
            a0 += ce_s[xt][24] * wih_r[24];
#pragma unroll
            for (int k = 0; k < 24; k += 4) {
                a0 += h_s[dir][k + 0] * whh_r[k + 0];
                a1 += h_s[dir][k + 1] * whh_r[k + 1];
                a2 += h_s[dir][k + 2] * whh_r[k + 2];
                a3 += h_s[dir][k + 3] * whh_r[k + 3];
            }
            a1 += h_s[dir][24] * whh_r[24];
            gate_s[dir][g] = (a0 + a1) + (a2 + a3);
        }
        __syncthreads();
        if (g < NCH) {
            float i_ = sigm(gate_s[dir][g]);
            float f_ = sigm(gate_s[dir][25 + g]);
            float gg = tanh_f(gate_s[dir][50 + g]);
            float o_ = sigm(gate_s[dir][75 + g]);
            c = f_ * c + i_ * gg;
            h_s[dir][g] = o_ * tanh_f(c);
        }
        __syncthreads();
    }

    if (g < NCH) g_char_feat[word * 50 + dir * NCH + g] = h_s[dir][g];
}

// ---------------------------------------------------------------------------
// K2: x = concat(word_emb[tok], char_feat[recover])
// ---------------------------------------------------------------------------
__global__ void build_x_kernel(const int* __restrict__ tok,
                               const int* __restrict__ recover,
                               const float* __restrict__ word_emb)
{
    int e = blockIdx.x * blockDim.x + threadIdx.x;
    if (e >= NBT * NDW) return;
    int r = e / NDW, c = e % NDW;
    float v;
    if (c < NWE) v = word_emb[(long long)tok[r] * NWE + c];
    else         v = g_char_feat[recover[r] * 50 + (c - NWE)];
    g_x[e] = v;
}

// ---------------------------------------------------------------------------
// K3: SGEMM  C[16384,400] = g_x[16384,150] @ W[150,400] + bias
// Tiled 64x64, 256 threads, 4x4 per thread, fma.rn.f32x2 mainloop.
// A tile stored in smem DUPLICATED as {v,v} u64 so the packed multiplier
// costs zero instructions per k-iter; B pairs come straight from LDS.64.
// Bit-exact vs scalar FFMA version.
// ---------------------------------------------------------------------------
__global__ void sgemm_kernel(const float* __restrict__ W,
                             const float* __restrict__ bias, int which)
{
    const int M = NBT, N = 400, K = NDW;
    __shared__ u64 As2[16][64];           // {v,v} duplicated A
    __shared__ float Bs[16][68];
    int tid = threadIdx.x;
    int tx = tid & 15, ty = tid >> 4;
    int cbase = blockIdx.x * 64, rbase = blockIdx.y * 64;
    float* C = which ? g_xw_b : g_xw_f;

    u64 acc[4][2];
#pragma unroll
    for (int i = 0; i < 4; i++) { acc[i][0] = 0ull; acc[i][1] = 0ull; }

    for (int kk = 0; kk < K; kk += 16) {
#pragma unroll
        for (int l = 0; l < 4; l++) {
            int e = tid + 256 * l;
            int r = e >> 4, k = e & 15;
            float v = (kk + k < K) ? g_x[(rbase + r) * K + kk + k] : 0.f;
            As2[k][r] = pack2(v, v);
        }
#pragma unroll
        for (int l = 0; l < 4; l++) {
            int e = tid + 256 * l;
            int k = e >> 6, c = e & 63;
            int col = cbase + c;
            Bs[k][c] = (kk + k < K && col < N) ? W[(kk + k) * N + col] : 0.f;
        }
        __syncthreads();
#pragma unroll
        for (int k = 0; k < 16; k++) {
            const ulonglong2* ap = reinterpret_cast<const ulonglong2*>(&As2[k][ty * 4]);
            ulonglong2 ra01 = ap[0];   // .x = {a0,a0}, .y = {a1,a1}
            ulonglong2 ra23 = ap[1];   // .x = {a2,a2}, .y = {a3,a3}
            const u64* bp = reinterpret_cast<const u64*>(&Bs[k][tx * 4]);
            u64 rb01 = bp[0], rb23 = bp[1];
            ffma2(acc[0][0], ra01.x, rb01); ffma2(acc[0][1], ra01.x, rb23);
            ffma2(acc[1][0], ra01.y, rb01); ffma2(acc[1][1], ra01.y, rb23);
            ffma2(acc[2][0], ra23.x, rb01); ffma2(acc[2][1], ra23.x, rb23);
            ffma2(acc[3][0], ra23.y, rb01); ffma2(acc[3][1], ra23.y, rb23);
        }
        __syncthreads();
    }
#pragma unroll
    for (int i = 0; i < 4; i++) {
        int row = rbase + ty * 4 + i;
        float c0, c1, c2, c3;
        unpack2(acc[i][0], c0, c1);
        unpack2(acc[i][1], c2, c3);
        float cv[4] = {c0, c1, c2, c3};
#pragma unroll
        for (int j = 0; j < 4; j++) {
            int col = cbase + tx * 4 + j;
            if (col < N && row < M) C[row * N + col] = cv[j] + bias[col];
        }
    }
}

// ---------------------------------------------------------------------------
// K4: word BiLSTM recurrence. One block per (seq, dir); 400 threads = gates.
// Whh column packed as 50 u64 {w[k],w[k+1]} in registers; h pairs read as
// LDS.64 (already adjacent in smem). fma.rn.f32x2 halves FFMA-pipe load;
// 2 independent packed chains keep dependency latency ~100 cyc/step.
// Input projection (incl. bias) already folded into g_xw_{f,b}.
// ---------------------------------------------------------------------------
__global__ __launch_bounds__(400, 1)
void word_lstm_kernel(const float* __restrict__ whh_f, const float* __restrict__ whh_b)
{
    int b = blockIdx.x;
    int dir = blockIdx.y;
    const float* whh = dir ? whh_b : whh_f;
    const float* xw = dir ? g_xw_b : g_xw_f;
    int g = threadIdx.x;  // 0..399

    u64 w2[NWH / 2];
#pragma unroll
    for (int k = 0; k < NWH; k += 2)
        w2[k >> 1] = pack2(whh[k * 400 + g], whh[(k + 1) * 400 + g]);

    __shared__ __align__(16) float h_s[NWH];
    __shared__ float gate_s[400];
    float c = 0.f;
    if (g < NWH) h_s[g] = 0.f;
    __syncthreads();

    const u64* hp = reinterpret_cast<const u64*>(h_s);

    for (int t = 0; t < NT; t++) {
        int tt = dir ? (NT - 1 - t) : t;
        float x0 = xw[(b * NT + tt) * 400 + g];
        u64 acc01 = 0ull, acc23 = 0ull;
#pragma unroll
        for (int k = 0; k < NWH / 2; k += 2) {
            ffma2(acc01, hp[k], w2[k]);
            ffma2(acc23, hp[k + 1], w2[k + 1]);
        }
        float a0, a1, a2, a3;
        unpack2(acc01, a0, a1);
        unpack2(acc23, a2, a3);
        gate_s[g] = x0 + ((a0 + a1) + (a2 + a3));
        __syncthreads();
        if (g < NWH) {
            float i_ = sigm(gate_s[g]);
            float f_ = sigm(gate_s[100 + g]);
            float gg = tanh_f(gate_s[200 + g]);
            float o_ = sigm(gate_s[300 + g]);
            c = f_ * c + i_ * gg;
            float hv = o_ * tanh_f(c);
            h_s[g] = hv;
            g_seq[(b * NT + tt) * 200 + dir * NWH + g] = hv;
        }
        __syncthreads();
    }
}

// ---------------------------------------------------------------------------
// K5: emissions em = seq @ W_tag + b_tag. Block handles 32 rows from smem.
// ---------------------------------------------------------------------------
__global__ void emissions_kernel(const float* __restrict__ Wt, const float* __restrict__ bt)
{
    __shared__ float wt_s[200 * NL];
    __shared__ float rows_s[32][200];
    int base_row = blockIdx.x * 32;
    for (int e = threadIdx.x; e < 200 * NL; e += 256) wt_s[e] = Wt[e];
    for (int e = threadIdx.x; e < 32 * 200; e += 256)
        rows_s[e / 200][e % 200] = g_seq[(base_row + e / 200) * 200 + e % 200];
    __syncthreads();
    for (int o = threadIdx.x; o < 32 * NL; o += 256) {
        int r = o / NL, l = o % NL;
        float acc = bt[l];
#pragma unroll 8
        for (int k = 0; k < 200; k++) acc += rows_s[r][k] * wt_s[k * NL + l];
        g_em[(base_row + r) * NL + l] = acc;
    }
}

// ---------------------------------------------------------------------------
// K6: CRF NLL per batch element. One warp per batch row.
// ---------------------------------------------------------------------------
__global__ void crf_kernel(const int* __restrict__ tags,
                           const float* __restrict__ trans,
                           const float* __restrict__ startv,
                           const float* __restrict__ endv)
{
    int b = blockIdx.x;
    int j = threadIdx.x;  // 0..31
    const float L2E = 1.4426950408889634f;

    // ---- gold path score ----
    float gold = 0.f;
    for (int t = j; t < NT; t += 32) {
        int tg = tags[b * NT + t];
        gold += g_em[(b * NT + t) * NL + tg];
        if (t < NT - 1) gold += trans[tg * NL + tags[b * NT + t + 1]];
    }
    if (j == 0) gold += startv[tags[b * NT]] + endv[tags[b * NT + NT - 1]];
#pragma unroll
    for (int o = 16; o > 0; o >>= 1) gold += __shfl_xor_sync(0xffffffffu, gold, o);

    // ---- forward algorithm ----
    float tr[NL];
#pragma unroll
    for (int i = 0; i < NL; i++) tr[i] = 0.f;
    if (j < NL) {
#pragma unroll
        for (int i = 0; i < NL; i++) tr[i] = trans[i * NL + j];
    }
    float a = (j < NL) ? (startv[j] + g_em[(b * NT) * NL + j]) : -1e30f;

    for (int t = 1; t < NT; t++) {
        float v[NL];
        float m = -1e30f;
#pragma unroll
        for (int i = 0; i < NL; i++) {
            float ai = __shfl_sync(0xffffffffu, a, i);
            v[i] = ai + tr[i];
            m = fmaxf(m, v[i]);
        }
        float s = 0.f;
#pragma unroll
        for (int i = 0; i < NL; i++) s += exp2f((v[i] - m) * L2E);
        float na = m + __logf(s) + ((j < NL) ? g_em[(b * NT + t) * NL + j] : 0.f);
        a = (j < NL) ? na : -1e30f;
    }

    float z = (j < NL) ? a + endv[j] : -1e30f;
    float m = z;
#pragma unroll
    for (int o = 16; o > 0; o >>= 1) m = fmaxf(m, __shfl_xor_sync(0xffffffffu, m, o));
    float s = exp2f((z - m) * L2E);
#pragma unroll
    for (int o = 16; o > 0; o >>= 1) s += __shfl_xor_sync(0xffffffffu, s, o);
    if (j == 0) g_crf[b] = (m + __logf(s)) - gold;
}

// ---------------------------------------------------------------------------
// K7: deterministic final reduction
// ---------------------------------------------------------------------------
__global__ void final_reduce(float* out)
{
    if (threadIdx.x == 0) {
        float s = 0.f;
        for (int b = 0; b < NB; b++) s += g_crf[b];
        out[0] = s;
    }
}

extern "C" void kernel_launch(void* const* d_in, const int* in_sizes, int n_in,
                              void* d_out, int out_size)
{
    const int* tok          = (const int*)d_in[0];
    const int* tag          = (const int*)d_in[1];
    // d_in[2] lengths: all T, unused
    const int* char_tensor  = (const int*)d_in[3];
    const int* char_lengths = (const int*)d_in[4];
    const int* recover      = (const int*)d_in[5];
    const float* word_emb   = (const float*)d_in[6];
    const float* char_emb   = (const float*)d_in[7];
    const float* cWih_f = (const float*)d_in[8];
    const float* cWhh_f = (const float*)d_in[9];
    const float* cb_f   = (const float*)d_in[10];
    const float* cWih_b = (const float*)d_in[11];
    const float* cWhh_b = (const float*)d_in[12];
    const float* cb_b   = (const float*)d_in[13];
    const float* wWih_f = (const float*)d_in[14];
    const float* wWhh_f = (const float*)d_in[15];
    const float* wb_f   = (const float*)d_in[16];
    const float* wWih_b = (const float*)d_in[17];
    const float* wWhh_b = (const float*)d_in[18];
    const float* wb_b   = (const float*)d_in[19];
    const float* W_tag  = (const float*)d_in[20];
    const float* b_tag  = (const float*)d_in[21];
    const float* trans  = (const float*)d_in[22];
    const float* startv = (const float*)d_in[23];
    const float* endv   = (const float*)d_in[24];
    float* out = (float*)d_out;

    char_lstm_kernel<<<NBT, 256>>>(char_tensor, char_lengths, char_emb,
                                   cWih_f, cWhh_f, cb_f, cWih_b, cWhh_b, cb_b);
    build_x_kernel<<<(NBT * NDW + 255) / 256, 256>>>(tok, recover, word_emb);
    sgemm_kernel<<<dim3(7, NBT / 64), 256>>>(wWih_f, wb_f, 0);
    sgemm_kernel<<<dim3(7, NBT / 64), 256>>>(wWih_b, wb_b, 1);
    word_lstm_kernel<<<dim3(NB, 2), 400>>>(wWhh_f, wWhh_b);
    emissions_kernel<<<NBT / 32, 256>>>(W_tag, b_tag);
    crf_kernel<<<NB, 32>>>(tag, trans, startv, endv);
    final_reduce<<<1, 32>>>(out);
}

// round 8
// speedup vs baseline: 1.1001x; 1.1001x over previous
#include <cuda_runtime.h>
#include <math.h>

// Problem constants
#define NB   64        // batch
#define NT   256       // seq len
#define NBT  16384     // NB*NT
#define NTC  16        // char seq len
#define NCE  25        // char embed
#define NCH  25        // char hidden
#define NWE  100       // word embed
#define NWH  100       // word hidden
#define NDW  150       // word-LSTM input dim
#define NL   25        // labels

typedef unsigned long long u64;

// Scratch (device globals; no allocations allowed)
__device__ float g_char_feat[NBT * 50];
__device__ float g_x[NBT * NDW];
__device__ float g_xw_f[NBT * 400];
__device__ float g_xw_b[NBT * 400];
__device__ float g_seq[NBT * 200];
__device__ float g_em[NBT * NL];
__device__ float g_crf[NB];

// Accurate activations: recurrences amplify per-step error over 256 steps,
// and these run on a small minority of lanes, so accuracy is ~free.
__device__ __forceinline__ float sigm(float x) { return 1.f / (1.f + expf(-x)); }
__device__ __forceinline__ float tanh_f(float x) { return tanhf(x); }

// ---- packed fp32x2 helpers (sm_103a): two EXACT fp32 FMAs per instruction ----
__device__ __forceinline__ u64 pack2(float lo, float hi) {
    u64 r; asm("mov.b64 %0, {%1, %2};" : "=l"(r) : "f"(lo), "f"(hi)); return r;
}
__device__ __forceinline__ void unpack2(u64 v, float& lo, float& hi) {
    asm("mov.b64 {%0, %1}, %2;" : "=f"(lo), "=f"(hi) : "l"(v));
}
__device__ __forceinline__ void ffma2(u64& d, u64 a, u64 b) {
    asm("fma.rn.f32x2 %0, %1, %2, %0;" : "+l"(d) : "l"(a), "l"(b));
}

// ---------------------------------------------------------------------------
// K1: char BiLSTM. 8 words per block: weight registers (40 KB/block worth of
// gmem reads) are loaded ONCE and reused across 8 words, cutting weight L2
// traffic 8x (~650 MB -> ~82 MB). Threads 0-127 = fwd gates, 128-255 = bwd.
// Runs only `len` steps per word (hidden at len-1 depends only on prefix).
// ---------------------------------------------------------------------------
#define WPB 8

__global__ void char_lstm_kernel(const int* __restrict__ char_tensor,
                                 const int* __restrict__ char_lengths,
                                 const float* __restrict__ char_emb,
                                 const float* __restrict__ wih_f, const float* __restrict__ whh_f,
                                 const float* __restrict__ b_f,
                                 const float* __restrict__ wih_b, const float* __restrict__ whh_b,
                                 const float* __restrict__ b_b)
{
    int tid = threadIdx.x;
    int dir = tid >> 7;       // 0 fwd, 1 bwd
    int g = tid & 127;        // gate id (valid < 100)

    __shared__ float ce_s[NTC][NCE];
    __shared__ int cidx[NTC];
    __shared__ float h_s[2][NCH];
    __shared__ float gate_s[2][100];

    // Load weights once; reuse for all WPB words.
    float wih_r[NCE], whh_r[NCH], br = 0.f;
    if (g < 100) {
        const float* wih = dir ? wih_b : wih_f;
        const float* whh = dir ? whh_b : whh_f;
        br = (dir ? b_b : b_f)[g];
#pragma unroll
        for (int k = 0; k < NCE; k++) wih_r[k] = wih[k * 100 + g];
#pragma unroll
        for (int k = 0; k < NCH; k++) whh_r[k] = whh[k * 100 + g];
    }

    for (int w = 0; w < WPB; w++) {
        int word = blockIdx.x * WPB + w;
        int len = char_lengths[word];

        if (tid < NTC) cidx[tid] = char_tensor[word * NTC + tid];
        __syncthreads();
        for (int e = tid; e < NTC * NCE; e += 256) {
            int t = e / NCE, k = e % NCE;
            ce_s[t][k] = char_emb[cidx[t] * NCE + k];
        }

        float c = 0.f;
        if (g < NCH) h_s[dir][g] = 0.f;
        __syncthreads();

        for (int t = 0; t < len; t++) {
            int xt = dir ? (len - 1 - t) : t;
            if (g < 100) {
                float a0 = br, a1 = 0.f, a2 = 0.f, a3 = 0.f;
#pragma unroll
                for (int k = 0; k < 24; k += 4) {
                    a0 += ce_s[xt][k + 0] * wih_r[k + 0];
                    a1 += ce_s[xt][k + 1] * wih_r[k + 1];
                    a2 += ce_s[xt][k + 2] * wih_r[k + 2];
                    a3 += ce_s[xt][k + 3] * wih_r[k + 3];
                }
                a0 += ce_s[xt][24] * wih_r[24];
#pragma unroll
                for (int k = 0; k < 24; k += 4) {
                    a0 += h_s[dir][k + 0] * whh_r[k + 0];
                    a1 += h_s[dir][k + 1] * whh_r[k + 1];
                    a2 += h_s[dir][k + 2] * whh_r[k + 2];
                    a3 += h_s[dir][k + 3] * whh_r[k + 3];
                }
                a1 += h_s[dir][24] * whh_r[24];
                gate_s[dir][g] = (a0 + a1) + (a2 + a3);
            }
            __syncthreads();
            if (g < NCH) {
                float i_ = sigm(gate_s[dir][g]);
                float f_ = sigm(gate_s[dir][25 + g]);
                float gg = tanh_f(gate_s[dir][50 + g]);
                float o_ = sigm(gate_s[dir][75 + g]);
                c = f_ * c + i_ * gg;
                h_s[dir][g] = o_ * tanh_f(c);
            }
            __syncthreads();
        }

        if (g < NCH) g_char_feat[word * 50 + dir * NCH + g] = h_s[dir][g];
        __syncthreads();  // protect ce_s/cidx/h_s before next word overwrites
    }
}

// ---------------------------------------------------------------------------
// K2: x = concat(word_emb[tok], char_feat[recover])
// ---------------------------------------------------------------------------
__global__ void build_x_kernel(const int* __restrict__ tok,
                               const int* __restrict__ recover,
                               const float* __restrict__ word_emb)
{
    int e = blockIdx.x * blockDim.x + threadIdx.x;
    if (e >= NBT * NDW) return;
    int r = e / NDW, c = e % NDW;
    float v;
    if (c < NWE) v = word_emb[(long long)tok[r] * NWE + c];
    else         v = g_char_feat[recover[r] * 50 + (c - NWE)];
    g_x[e] = v;
}

// ---------------------------------------------------------------------------
// K3: SGEMM  C[16384,400] = g_x[16384,150] @ W[150,400] + bias, both dirs via z.
// Tile 128x64, BK=16, 256 threads, 8 rows x 4 cols per thread.
// Row-paired f32x2 accumulators {C[r],C[r+1]}: A multiplier is a NATIVE
// contiguous u64 pair from smem (no dup cost); B stored duplicated {b,b}.
// Register-staged prefetch hides LDG latency. fma-pipe bound by design.
// ---------------------------------------------------------------------------
#define BM 128
#define BN 64
#define BK 16

__global__ __launch_bounds__(256, 3)
void sgemm_kernel(const float* __restrict__ Wf, const float* __restrict__ bf,
                  const float* __restrict__ Wb, const float* __restrict__ bb)
{
    const int K = NDW, N = 400;
    const int which = blockIdx.z;
    const float* W    = which ? Wb : Wf;
    const float* bias = which ? bb : bf;
    float* C          = which ? g_xw_b : g_xw_f;

    __shared__ float As[BK][BM + 4];   // pad 4: 16B-aligned rows
    __shared__ u64   Bs2[BK][BN];      // {b,b} duplicated

    int tid = threadIdx.x;
    int tx = tid & 15;                 // 16 col-groups of 4
    int ty = tid >> 4;                 // 16 row-groups of 8
    int cbase = blockIdx.x * BN, rbase = blockIdx.y * BM;

    u64 acc[4][4];                     // [row-pair][col]
#pragma unroll
    for (int i = 0; i < 4; i++)
#pragma unroll
        for (int j = 0; j < 4; j++) acc[i][j] = 0ull;

    int ak = tid & 15, ar = tid >> 4;          // A: k fast (gmem-coalesced)
    int bc = tid & 63, bk = tid >> 6;          // B: c fast (gmem-coalesced)

    float aReg[8], bReg[4];
    const int NSTAGE = (K + BK - 1) / BK;      // 10

    // prefetch stage 0
    {
        int kk = 0;
#pragma unroll
        for (int l = 0; l < 8; l++) {
            int k = ak, r = ar + l * 16;
            aReg[l] = (kk + k < K) ? g_x[(rbase + r) * K + kk + k] : 0.f;
        }
#pragma unroll
        for (int l = 0; l < 4; l++) {
            int k = bk + l * 4, col = cbase + bc;
            bReg[l] = (kk + k < K && col < N) ? W[(kk + k) * N + col] : 0.f;
        }
    }

    for (int s = 0; s < NSTAGE; s++) {
#pragma unroll
        for (int l = 0; l < 8; l++) As[ak][ar + l * 16] = aReg[l];
#pragma unroll
        for (int l = 0; l < 4; l++) Bs2[bk + l * 4][bc] = pack2(bReg[l], bReg[l]);
        __syncthreads();

        if (s + 1 < NSTAGE) {
            int kk = (s + 1) * BK;
#pragma unroll
            for (int l = 0; l < 8; l++) {
                int k = ak, r = ar + l * 16;
                aReg[l] = (kk + k < K) ? g_x[(rbase + r) * K + kk + k] : 0.f;
            }
#pragma unroll
            for (int l = 0; l < 4; l++) {
                int k = bk + l * 4, col = cbase + bc;
                bReg[l] = (kk + k < K && col < N) ? W[(kk + k) * N + col] : 0.f;
            }
        }

#pragma unroll
        for (int k = 0; k < BK; k++) {
            const u64* ap = reinterpret_cast<const u64*>(&As[k][ty * 8]);
            u64 a0 = ap[0], a1 = ap[1], a2 = ap[2], a3 = ap[3];
            const u64* bp = &Bs2[k][tx * 4];
            u64 b0 = bp[0], b1 = bp[1], b2 = bp[2], b3 = bp[3];
            ffma2(acc[0][0], a0, b0); ffma2(acc[0][1], a0, b1);
            ffma2(acc[0][2], a0, b2); ffma2(acc[0][3], a0, b3);
            ffma2(acc[1][0], a1, b0); ffma2(acc[1][1], a1, b1);
            ffma2(acc[1][2], a1, b2); ffma2(acc[1][3], a1, b3);
            ffma2(acc[2][0], a2, b0); ffma2(acc[2][1], a2, b1);
            ffma2(acc[2][2], a2, b2); ffma2(acc[2][3], a2, b3);
            ffma2(acc[3][0], a3, b0); ffma2(acc[3][1], a3, b1);
            ffma2(acc[3][2], a3, b2); ffma2(acc[3][3], a3, b3);
        }
        __syncthreads();
    }

#pragma unroll
    for (int i = 0; i < 4; i++) {
        int row0 = rbase + ty * 8 + i * 2;
#pragma unroll
        for (int j = 0; j < 4; j++) {
            int col = cbase + tx * 4 + j;
            if (col < N) {
                float lo, hi;
                unpack2(acc[i][j], lo, hi);
                float bv = bias[col];
                C[row0 * N + col]       = lo + bv;
                C[(row0 + 1) * N + col] = hi + bv;
            }
        }
    }
}

// ---------------------------------------------------------------------------
// K4: word BiLSTM recurrence. One block per (seq, dir); 400 threads = gates.
// xw for step t+1 is PREFETCHED into a register before step t's matvec, so
// the serial-step gmem latency (L2/DRAM) hides under compute + barriers.
// ---------------------------------------------------------------------------
__global__ __launch_bounds__(400, 1)
void word_lstm_kernel(const float* __restrict__ whh_f, const float* __restrict__ whh_b)
{
    int b = blockIdx.x;
    int dir = blockIdx.y;
    const float* whh = dir ? whh_b : whh_f;
    const float* xw = dir ? g_xw_b : g_xw_f;
    int g = threadIdx.x;  // 0..399

    u64 w2[NWH / 2];
#pragma unroll
    for (int k = 0; k < NWH; k += 2)
        w2[k >> 1] = pack2(whh[k * 400 + g], whh[(k + 1) * 400 + g]);

    __shared__ __align__(16) float h_s[NWH];
    __shared__ float gate_s[400];
    float c = 0.f;
    if (g < NWH) h_s[g] = 0.f;
    __syncthreads();

    const u64* hp = reinterpret_cast<const u64*>(h_s);

    long long idx0 = dir ? ((long long)(b * NT + NT - 1) * 400 + g)
                         : ((long long)(b * NT) * 400 + g);
    long long stride = dir ? -400 : 400;

    float x_cur = xw[idx0];

    for (int t = 0; t < NT; t++) {
        // prefetch next step's input (independent of everything below)
        float x_next = 0.f;
        if (t + 1 < NT) x_next = xw[idx0 + (long long)(t + 1) * stride];

        u64 acc01 = 0ull, acc23 = 0ull;
#pragma unroll
        for (int k = 0; k < NWH / 2; k += 2) {
            ffma2(acc01, hp[k], w2[k]);
            ffma2(acc23, hp[k + 1], w2[k + 1]);
        }
        float a0, a1, a2, a3;
        unpack2(acc01, a0, a1);
        unpack2(acc23, a2, a3);
        gate_s[g] = x_cur + ((a0 + a1) + (a2 + a3));
        __syncthreads();
        if (g < NWH) {
            float i_ = sigm(gate_s[g]);
            float f_ = sigm(gate_s[100 + g]);
            float gg = tanh_f(gate_s[200 + g]);
            float o_ = sigm(gate_s[300 + g]);
            c = f_ * c + i_ * gg;
            float hv = o_ * tanh_f(c);
            h_s[g] = hv;
            int tt = dir ? (NT - 1 - t) : t;
            g_seq[(b * NT + tt) * 200 + dir * NWH + g] = hv;
        }
        __syncthreads();
        x_cur = x_next;
    }
}

// ---------------------------------------------------------------------------
// K5: emissions em = seq @ W_tag + b_tag. Block handles 32 rows from smem.
// ---------------------------------------------------------------------------
__global__ void emissions_kernel(const float* __restrict__ Wt, const float* __restrict__ bt)
{
    __shared__ float wt_s[200 * NL];
    __shared__ float rows_s[32][200];
    int base_row = blockIdx.x * 32;
    for (int e = threadIdx.x; e < 200 * NL; e += 256) wt_s[e] = Wt[e];
    for (int e = threadIdx.x; e < 32 * 200; e += 256)
        rows_s[e / 200][e % 200] = g_seq[(base_row + e / 200) * 200 + e % 200];
    __syncthreads();
    for (int o = threadIdx.x; o < 32 * NL; o += 256) {
        int r = o / NL, l = o % NL;
        float acc = bt[l];
#pragma unroll 8
        for (int k = 0; k < 200; k++) acc += rows_s[r][k] * wt_s[k * NL + l];
        g_em[(base_row + r) * NL + l] = acc;
    }
}

// ---------------------------------------------------------------------------
// K6: CRF NLL per batch element. One warp per batch row.
// ---------------------------------------------------------------------------
__global__ void crf_kernel(const int* __restrict__ tags,
                           const float* __restrict__ trans,
                           const float* __restrict__ startv,
                           const float* __restrict__ endv)
{
    int b = blockIdx.x;
    int j = threadIdx.x;  // 0..31
    const float L2E = 1.4426950408889634f;

    // ---- gold path score ----
    float gold = 0.f;
    for (int t = j; t < NT; t += 32) {
        int tg = tags[b * NT + t];
        gold += g_em[(b * NT + t) * NL + tg];
        if (t < NT - 1) gold += trans[tg * NL + tags[b * NT + t + 1]];
    }
    if (j == 0) gold += startv[tags[b * NT]] + endv[tags[b * NT + NT - 1]];
#pragma unroll
    for (int o = 16; o > 0; o >>= 1) gold += __shfl_xor_sync(0xffffffffu, gold, o);

    // ---- forward algorithm ----
    float tr[NL];
#pragma unroll
    for (int i = 0; i < NL; i++) tr[i] = 0.f;
    if (j < NL) {
#pragma unroll
        for (int i = 0; i < NL; i++) tr[i] = trans[i * NL + j];
    }
    float a = (j < NL) ? (startv[j] + g_em[(b * NT) * NL + j]) : -1e30f;

    for (int t = 1; t < NT; t++) {
        float v[NL];
        float m = -1e30f;
#pragma unroll
        for (int i = 0; i < NL; i++) {
            float ai = __shfl_sync(0xffffffffu, a, i);
            v[i] = ai + tr[i];
            m = fmaxf(m, v[i]);
        }
        float s = 0.f;
#pragma unroll
        for (int i = 0; i < NL; i++) s += exp2f((v[i] - m) * L2E);
        float na = m + __logf(s) + ((j < NL) ? g_em[(b * NT + t) * NL + j] : 0.f);
        a = (j < NL) ? na : -1e30f;
    }

    float z = (j < NL) ? a + endv[j] : -1e30f;
    float m = z;
#pragma unroll
    for (int o = 16; o > 0; o >>= 1) m = fmaxf(m, __shfl_xor_sync(0xffffffffu, m, o));
    float s = exp2f((z - m) * L2E);
#pragma unroll
    for (int o = 16; o > 0; o >>= 1) s += __shfl_xor_sync(0xffffffffu, s, o);
    if (j == 0) g_crf[b] = (m + __logf(s)) - gold;
}

// ---------------------------------------------------------------------------
// K7: deterministic final reduction
// ---------------------------------------------------------------------------
__global__ void final_reduce(float* out)
{
    if (threadIdx.x == 0) {
        float s = 0.f;
        for (int b = 0; b < NB; b++) s += g_crf[b];
        out[0] = s;
    }
}

extern "C" void kernel_launch(void* const* d_in, const int* in_sizes, int n_in,
                              void* d_out, int out_size)
{
    const int* tok          = (const int*)d_in[0];
    const int* tag          = (const int*)d_in[1];
    // d_in[2] lengths: all T, unused
    const int* char_tensor  = (const int*)d_in[3];
    const int* char_lengths = (const int*)d_in[4];
    const int* recover      = (const int*)d_in[5];
    const float* word_emb   = (const float*)d_in[6];
    const float* char_emb   = (const float*)d_in[7];
    const float* cWih_f = (const float*)d_in[8];
    const float* cWhh_f = (const float*)d_in[9];
    const float* cb_f   = (const float*)d_in[10];
    const float* cWih_b = (const float*)d_in[11];
    const float* cWhh_b = (const float*)d_in[12];
    const float* cb_b   = (const float*)d_in[13];
    const float* wWih_f = (const float*)d_in[14];
    const float* wWhh_f = (const float*)d_in[15];
    const float* wb_f   = (const float*)d_in[16];
    const float* wWih_b = (const float*)d_in[17];
    const float* wWhh_b = (const float*)d_in[18];
    const float* wb_b   = (const float*)d_in[19];
    const float* W_tag  = (const float*)d_in[20];
    const float* b_tag  = (const float*)d_in[21];
    const float* trans  = (const float*)d_in[22];
    const float* startv = (const float*)d_in[23];
    const float* endv   = (const float*)d_in[24];
    float* out = (float*)d_out;

    char_lstm_kernel<<<NBT / WPB, 256>>>(char_tensor, char_lengths, char_emb,
                                         cWih_f, cWhh_f, cb_f, cWih_b, cWhh_b, cb_b);
    build_x_kernel<<<(NBT * NDW + 255) / 256, 256>>>(tok, recover, word_emb);
    sgemm_kernel<<<dim3(7, NBT / BM, 2), 256>>>(wWih_f, wb_f, wWih_b, wb_b);
    word_lstm_kernel<<<dim3(NB, 2), 400>>>(wWhh_f, wWhh_b);
    emissions_kernel<<<NBT / 32, 256>>>(W_tag, b_tag);
    crf_kernel<<<NB, 32>>>(tag, trans, startv, endv);
    final_reduce<<<1, 32>>>(out);
}

// round 15
// speedup vs baseline: 1.1285x; 1.0258x over previous
#include <cuda_runtime.h>
#include <math.h>

// Problem constants
#define NB   64        // batch
#define NT   256       // seq len
#define NBT  16384     // NB*NT
#define NTC  16        // char seq len
#define NCE  25        // char embed
#define NCH  25        // char hidden
#define NWE  100       // word embed
#define NWH  100       // word hidden
#define NDW  150       // word-LSTM input dim
#define NL   25        // labels

typedef unsigned long long u64;

// Scratch (device globals; no allocations allowed)
__device__ float g_char_feat[NBT * 50];
__device__ float g_x[NBT * NDW];
__device__ float g_xw_f[NBT * 400];
__device__ float g_xw_b[NBT * 400];
__device__ float g_seq[NBT * 200];
__device__ float g_em[NBT * NL];
__device__ float g_crf[NB];

// Accurate activations (rel_err margin is huge; recurrences need the accuracy).
__device__ __forceinline__ float sigm(float x) { return 1.f / (1.f + expf(-x)); }
__device__ __forceinline__ float tanh_f(float x) { return tanhf(x); }

// ---- packed fp32x2 helpers (sm_103a): two EXACT fp32 FMAs per instruction ----
__device__ __forceinline__ u64 pack2(float lo, float hi) {
    u64 r; asm("mov.b64 %0, {%1, %2};" : "=l"(r) : "f"(lo), "f"(hi)); return r;
}
__device__ __forceinline__ void unpack2(u64 v, float& lo, float& hi) {
    asm("mov.b64 {%0, %1}, %2;" : "=f"(lo), "=f"(hi) : "l"(v));
}
__device__ __forceinline__ void ffma2(u64& d, u64 a, u64 b) {
    asm("fma.rn.f32x2 %0, %1, %2, %0;" : "+l"(d) : "l"(a), "l"(b));
}

// ---------------------------------------------------------------------------
// K1: char BiLSTM. 8 words per block (weights in regs, reused). Activations
// are applied by EACH gate thread in the wide phase (100 lanes/dir), leaving
// only c-update + one tanh in the narrow 25-lane phase.
// ---------------------------------------------------------------------------
#define WPB 8

__global__ void char_lstm_kernel(const int* __restrict__ char_tensor,
                                 const int* __restrict__ char_lengths,
                                 const float* __restrict__ char_emb,
                                 const float* __restrict__ wih_f, const float* __restrict__ whh_f,
                                 const float* __restrict__ b_f,
                                 const float* __restrict__ wih_b, const float* __restrict__ whh_b,
                                 const float* __restrict__ b_b)
{
    int tid = threadIdx.x;
    int dir = tid >> 7;       // 0 fwd, 1 bwd
    int g = tid & 127;        // gate id (valid < 100)

    __shared__ float ce_s[NTC][NCE];
    __shared__ int cidx[NTC];
    __shared__ float h_s[2][NCH];
    __shared__ float gate_s[2][100];

    // Load weights once; reuse for all WPB words.
    float wih_r[NCE], whh_r[NCH], br = 0.f;
    if (g < 100) {
        const float* wih = dir ? wih_b : wih_f;
        const float* whh = dir ? whh_b : whh_f;
        br = (dir ? b_b : b_f)[g];
#pragma unroll
        for (int k = 0; k < NCE; k++) wih_r[k] = wih[k * 100 + g];
#pragma unroll
        for (int k = 0; k < NCH; k++) whh_r[k] = whh[k * 100 + g];
    }
    int gtype = g / 25;       // 0:i 1:f 2:g 3:o

    for (int w = 0; w < WPB; w++) {
        int word = blockIdx.x * WPB + w;
        int len = char_lengths[word];

        if (tid < NTC) cidx[tid] = char_tensor[word * NTC + tid];
        __syncthreads();
        for (int e = tid; e < NTC * NCE; e += 256) {
            int t = e / NCE, k = e % NCE;
            ce_s[t][k] = char_emb[cidx[t] * NCE + k];
        }

        float c = 0.f;
        if (g < NCH) h_s[dir][g] = 0.f;
        __syncthreads();

        for (int t = 0; t < len; t++) {
            int xt = dir ? (len - 1 - t) : t;
            if (g < 100) {
                float a0 = br, a1 = 0.f, a2 = 0.f, a3 = 0.f;
#pragma unroll
                for (int k = 0; k < 24; k += 4) {
                    a0 += ce_s[xt][k + 0] * wih_r[k + 0];
                    a1 += ce_s[xt][k + 1] * wih_r[k + 1];
                    a2 += ce_s[xt][k + 2] * wih_r[k + 2];
                    a3 += ce_s[xt][k + 3] * wih_r[k + 3];
                }
                a0 += ce_s[xt][24] * wih_r[24];
#pragma unroll
                for (int k = 0; k < 24; k += 4) {
                    a0 += h_s[dir][k + 0] * whh_r[k + 0];
                    a1 += h_s[dir][k + 1] * whh_r[k + 1];
                    a2 += h_s[dir][k + 2] * whh_r[k + 2];
                    a3 += h_s[dir][k + 3] * whh_r[k + 3];
                }
                a1 += h_s[dir][24] * whh_r[24];
                float raw = (a0 + a1) + (a2 + a3);
                // activation in the WIDE phase (transcendentals pipelined over 100 lanes)
                gate_s[dir][g] = (gtype == 2) ? tanh_f(raw) : sigm(raw);
            }
            __syncthreads();
            if (g < NCH) {
                float i_ = gate_s[dir][g];
                float f_ = gate_s[dir][25 + g];
                float gg = gate_s[dir][50 + g];
                float o_ = gate_s[dir][75 + g];
                c = f_ * c + i_ * gg;
                h_s[dir][g] = o_ * tanh_f(c);
            }
            __syncthreads();
        }

        if (g < NCH) g_char_feat[word * 50 + dir * NCH + g] = h_s[dir][g];
        __syncthreads();  // protect ce_s/cidx/h_s before next word overwrites
    }
}

// ---------------------------------------------------------------------------
// K2: x = concat(word_emb[tok], char_feat[recover])
// ---------------------------------------------------------------------------
__global__ void build_x_kernel(const int* __restrict__ tok,
                               const int* __restrict__ recover,
                               const float* __restrict__ word_emb)
{
    int e = blockIdx.x * blockDim.x + threadIdx.x;
    if (e >= NBT * NDW) return;
    int r = e / NDW, c = e % NDW;
    float v;
    if (c < NWE) v = word_emb[(long long)tok[r] * NWE + c];
    else         v = g_char_feat[recover[r] * 50 + (c - NWE)];
    g_x[e] = v;
}

// ---------------------------------------------------------------------------
// K3: SGEMM  C[16384,400] = g_x[16384,150] @ W[150,400] + bias, both dirs via z.
// Tile 128x64, BK=16, 256 threads, 8 rows x 4 cols per thread, f32x2 mainloop.
// ---------------------------------------------------------------------------
#define BM 128
#define BN 64
#define BK 16

__global__ __launch_bounds__(256, 3)
void sgemm_kernel(const float* __restrict__ Wf, const float* __restrict__ bf,
                  const float* __restrict__ Wb, const float* __restrict__ bb)
{
    const int K = NDW, N = 400;
    const int which = blockIdx.z;
    const float* W    = which ? Wb : Wf;
    const float* bias = which ? bb : bf;
    float* C          = which ? g_xw_b : g_xw_f;

    __shared__ float As[BK][BM + 4];   // pad 4: 16B-aligned rows
    __shared__ u64   Bs2[BK][BN];      // {b,b} duplicated

    int tid = threadIdx.x;
    int tx = tid & 15;                 // 16 col-groups of 4
    int ty = tid >> 4;                 // 16 row-groups of 8
    int cbase = blockIdx.x * BN, rbase = blockIdx.y * BM;

    u64 acc[4][4];                     // [row-pair][col]
#pragma unroll
    for (int i = 0; i < 4; i++)
#pragma unroll
        for (int j = 0; j < 4; j++) acc[i][j] = 0ull;

    int ak = tid & 15, ar = tid >> 4;          // A: k fast (gmem-coalesced)
    int bc = tid & 63, bk = tid >> 6;          // B: c fast (gmem-coalesced)

    float aReg[8], bReg[4];
    const int NSTAGE = (K + BK - 1) / BK;      // 10

    // prefetch stage 0
    {
        int kk = 0;
#pragma unroll
        for (int l = 0; l < 8; l++) {
            int k = ak, r = ar + l * 16;
            aReg[l] = (kk + k < K) ? g_x[(rbase + r) * K + kk + k] : 0.f;
        }
#pragma unroll
        for (int l = 0; l < 4; l++) {
            int k = bk + l * 4, col = cbase + bc;
            bReg[l] = (kk + k < K && col < N) ? W[(kk + k) * N + col] : 0.f;
        }
    }

    for (int s = 0; s < NSTAGE; s++) {
#pragma unroll
        for (int l = 0; l < 8; l++) As[ak][ar + l * 16] = aReg[l];
#pragma unroll
        for (int l = 0; l < 4; l++) Bs2[bk + l * 4][bc] = pack2(bReg[l], bReg[l]);
        __syncthreads();

        if (s + 1 < NSTAGE) {
            int kk = (s + 1) * BK;
#pragma unroll
            for (int l = 0; l < 8; l++) {
                int k = ak, r = ar + l * 16;
                aReg[l] = (kk + k < K) ? g_x[(rbase + r) * K + kk + k] : 0.f;
            }
#pragma unroll
            for (int l = 0; l < 4; l++) {
                int k = bk + l * 4, col = cbase + bc;
                bReg[l] = (kk + k < K && col < N) ? W[(kk + k) * N + col] : 0.f;
            }
        }

#pragma unroll
        for (int k = 0; k < BK; k++) {
            const u64* ap = reinterpret_cast<const u64*>(&As[k][ty * 8]);
            u64 a0 = ap[0], a1 = ap[1], a2 = ap[2], a3 = ap[3];
            const u64* bp = &Bs2[k][tx * 4];
            u64 b0 = bp[0], b1 = bp[1], b2 = bp[2], b3 = bp[3];
            ffma2(acc[0][0], a0, b0); ffma2(acc[0][1], a0, b1);
            ffma2(acc[0][2], a0, b2); ffma2(acc[0][3], a0, b3);
            ffma2(acc[1][0], a1, b0); ffma2(acc[1][1], a1, b1);
            ffma2(acc[1][2], a1, b2); ffma2(acc[1][3], a1, b3);
            ffma2(acc[2][0], a2, b0); ffma2(acc[2][1], a2, b1);
            ffma2(acc[2][2], a2, b2); ffma2(acc[2][3], a2, b3);
            ffma2(acc[3][0], a3, b0); ffma2(acc[3][1], a3, b1);
            ffma2(acc[3][2], a3, b2); ffma2(acc[3][3], a3, b3);
        }
        __syncthreads();
    }

#pragma unroll
    for (int i = 0; i < 4; i++) {
        int row0 = rbase + ty * 8 + i * 2;
#pragma unroll
        for (int j = 0; j < 4; j++) {
            int col = cbase + tx * 4 + j;
            if (col < N) {
                float lo, hi;
                unpack2(acc[i][j], lo, hi);
                float bv = bias[col];
                C[row0 * N + col]       = lo + bv;
                C[(row0 + 1) * N + col] = hi + bv;
            }
        }
    }
}

// ---------------------------------------------------------------------------
// K4: word BiLSTM recurrence. One block per (seq, dir); 400 threads = gates.
// Activation applied by EACH gate thread in the wide 400-lane phase;
// matvec split into FOUR independent ffma2 chains (depth ~13, ~52 cyc)
// instead of two (depth 25, ~100 cyc) — serial-step latency is wallclock.
// xw for step t+1 prefetched into a register before the matvec.
// ---------------------------------------------------------------------------
__global__ __launch_bounds__(400, 1)
void word_lstm_kernel(const float* __restrict__ whh_f, const float* __restrict__ whh_b)
{
    int b = blockIdx.x;
    int dir = blockIdx.y;
    const float* whh = dir ? whh_b : whh_f;
    const float* xw = dir ? g_xw_b : g_xw_f;
    int g = threadIdx.x;  // 0..399
    int gtype = g / 100;  // 0:i 1:f 2:g 3:o

    u64 w2[NWH / 2];
#pragma unroll
    for (int k = 0; k < NWH; k += 2)
        w2[k >> 1] = pack2(whh[k * 400 + g], whh[(k + 1) * 400 + g]);

    __shared__ __align__(16) float h_s[NWH];
    __shared__ float gate_s[400];
    float c = 0.f;
    if (g < NWH) h_s[g] = 0.f;
    __syncthreads();

    const u64* hp = reinterpret_cast<const u64*>(h_s);

    long long idx0 = dir ? ((long long)(b * NT + NT - 1) * 400 + g)
                         : ((long long)(b * NT) * 400 + g);
    long long stride = dir ? -400 : 400;

    float x_cur = xw[idx0];

    for (int t = 0; t < NT; t++) {
        // prefetch next step's input (independent of everything below)
        float x_next = 0.f;
        if (t + 1 < NT) x_next = xw[idx0 + (long long)(t + 1) * stride];

        // 4 independent packed chains: depth 12-13 each (~52 cyc) vs 25 (~100)
        u64 ac0 = 0ull, ac1 = 0ull, ac2 = 0ull, ac3 = 0ull;
#pragma unroll
        for (int k = 0; k < 48; k += 4) {
            ffma2(ac0, hp[k + 0], w2[k + 0]);
            ffma2(ac1, hp[k + 1], w2[k + 1]);
            ffma2(ac2, hp[k + 2], w2[k + 2]);
            ffma2(ac3, hp[k + 3], w2[k + 3]);
        }
        ffma2(ac0, hp[48], w2[48]);
        ffma2(ac1, hp[49], w2[49]);

        float p0, p1, p2, p3, p4, p5, p6, p7;
        unpack2(ac0, p0, p1);
        unpack2(ac1, p2, p3);
        unpack2(ac2, p4, p5);
        unpack2(ac3, p6, p7);
        float raw = x_cur + (((p0 + p1) + (p2 + p3)) + ((p4 + p5) + (p6 + p7)));
        // activation in the WIDE phase
        gate_s[g] = (gtype == 2) ? tanh_f(raw) : sigm(raw);
        __syncthreads();
        if (g < NWH) {
            float i_ = gate_s[g];
            float f_ = gate_s[100 + g];
            float gg = gate_s[200 + g];
            float o_ = gate_s[300 + g];
            c = f_ * c + i_ * gg;
            float hv = o_ * tanh_f(c);
            h_s[g] = hv;
            int tt = dir ? (NT - 1 - t) : t;
            g_seq[(b * NT + tt) * 200 + dir * NWH + g] = hv;
        }
        __syncthreads();
        x_cur = x_next;
    }
}

// ---------------------------------------------------------------------------
// K5: emissions em = seq @ W_tag + b_tag. Block handles 32 rows from smem.
// ---------------------------------------------------------------------------
__global__ void emissions_kernel(const float* __restrict__ Wt, const float* __restrict__ bt)
{
    __shared__ float wt_s[200 * NL];
    __shared__ float rows_s[32][200];
    int base_row = blockIdx.x * 32;
    for (int e = threadIdx.x; e < 200 * NL; e += 256) wt_s[e] = Wt[e];
    for (int e = threadIdx.x; e < 32 * 200; e += 256)
        rows_s[e / 200][e % 200] = g_seq[(base_row + e / 200) * 200 + e % 200];
    __syncthreads();
    for (int o = threadIdx.x; o < 32 * NL; o += 256) {
        int r = o / NL, l = o % NL;
        float acc = bt[l];
#pragma unroll 8
        for (int k = 0; k < 200; k++) acc += rows_s[r][k] * wt_s[k * NL + l];
        g_em[(base_row + r) * NL + l] = acc;
    }
}

// ---------------------------------------------------------------------------
// K6: CRF NLL per batch element. One warp per batch row.
// Per-step max and sum use PAIRWISE TREES (depth 5) instead of 25-deep
// serial chains — the 255-step serial recursion exposes those chains.
// ---------------------------------------------------------------------------
__device__ __forceinline__ float tree_max25(const float* v) {
    float r[NL];
#pragma unroll
    for (int i = 0; i < NL; i++) r[i] = v[i];
    int n = NL;
#pragma unroll
    while (n > 1) {
        int h = (n + 1) >> 1;
#pragma unroll
        for (int i = 0; i < n / 2; i++) r[i] = fmaxf(r[2 * i], r[2 * i + 1]);
        if (n & 1) r[n / 2] = r[n - 1];
        n = h;
    }
    return r[0];
}

__device__ __forceinline__ float tree_sum25(const float* v) {
    float r[NL];
#pragma unroll
    for (int i = 0; i < NL; i++) r[i] = v[i];
    int n = NL;
#pragma unroll
    while (n > 1) {
        int h = (n + 1) >> 1;
#pragma unroll
        for (int i = 0; i < n / 2; i++) r[i] = r[2 * i] + r[2 * i + 1];
        if (n & 1) r[n / 2] = r[n - 1];
        n = h;
    }
    return r[0];
}

__global__ void crf_kernel(const int* __restrict__ tags,
                           const float* __restrict__ trans,
                           const float* __restrict__ startv,
                           const float* __restrict__ endv)
{
    int b = blockIdx.x;
    int j = threadIdx.x;  // 0..31
    const float L2E = 1.4426950408889634f;

    // ---- gold path score ----
    float gold = 0.f;
    for (int t = j; t < NT; t += 32) {
        int tg = tags[b * NT + t];
        gold += g_em[(b * NT + t) * NL + tg];
        if (t < NT - 1) gold += trans[tg * NL + tags[b * NT + t + 1]];
    }
    if (j == 0) gold += startv[tags[b * NT]] + endv[tags[b * NT + NT - 1]];
#pragma unroll
    for (int o = 16; o > 0; o >>= 1) gold += __shfl_xor_sync(0xffffffffu, gold, o);

    // ---- forward algorithm ----
    float tr[NL];
#pragma unroll
    for (int i = 0; i < NL; i++) tr[i] = 0.f;
    if (j < NL) {
#pragma unroll
        for (int i = 0; i < NL; i++) tr[i] = trans[i * NL + j];
    }
    float a = (j < NL) ? (startv[j] + g_em[(b * NT) * NL + j]) : -1e30f;

    for (int t = 1; t < NT; t++) {
        float v[NL];
#pragma unroll
        for (int i = 0; i < NL; i++) {
            float ai = __shfl_sync(0xffffffffu, a, i);
            v[i] = ai + tr[i];
        }
        float m = tree_max25(v);
        float e[NL];
#pragma unroll
        for (int i = 0; i < NL; i++) e[i] = exp2f((v[i] - m) * L2E);
        float s = tree_sum25(e);
        float na = m + __logf(s) + ((j < NL) ? g_em[(b * NT + t) * NL + j] : 0.f);
        a = (j < NL) ? na : -1e30f;
    }

    float z = (j < NL) ? a + endv[j] : -1e30f;
    float m = z;
#pragma unroll
    for (int o = 16; o > 0; o >>= 1) m = fmaxf(m, __shfl_xor_sync(0xffffffffu, m, o));
    float s = exp2f((z - m) * L2E);
#pragma unroll
    for (int o = 16; o > 0; o >>= 1) s += __shfl_xor_sync(0xffffffffu, s, o);
    if (j == 0) g_crf[b] = (m + __logf(s)) - gold;
}

// ---------------------------------------------------------------------------
// K7: deterministic final reduction
// ---------------------------------------------------------------------------
__global__ void final_reduce(float* out)
{
    if (threadIdx.x == 0) {
        float s = 0.f;
        for (int b = 0; b < NB; b++) s += g_crf[b];
        out[0] = s;
    }
}

extern "C" void kernel_launch(void* const* d_in, const int* in_sizes, int n_in,
                              void* d_out, int out_size)
{
    const int* tok          = (const int*)d_in[0];
    const int* tag          = (const int*)d_in[1];
    // d_in[2] lengths: all T, unused
    const int* char_tensor  = (const int*)d_in[3];
    const int* char_lengths = (const int*)d_in[4];
    const int* recover      = (const int*)d_in[5];
    const float* word_emb   = (const float*)d_in[6];
    const float* char_emb   = (const float*)d_in[7];
    const float* cWih_f = (const float*)d_in[8];
    const float* cWhh_f = (const float*)d_in[9];
    const float* cb_f   = (const float*)d_in[10];
    const float* cWih_b = (const float*)d_in[11];
    const float* cWhh_b = (const float*)d_in[12];
    const float* cb_b   = (const float*)d_in[13];
    const float* wWih_f = (const float*)d_in[14];
    const float* wWhh_f = (const float*)d_in[15];
    const float* wb_f   = (const float*)d_in[16];
    const float* wWih_b = (const float*)d_in[17];
    const float* wWhh_b = (const float*)d_in[18];
    const float* wb_b   = (const float*)d_in[19];
    const float* W_tag  = (const float*)d_in[20];
    const float* b_tag  = (const float*)d_in[21];
    const float* trans  = (const float*)d_in[22];
    const float* startv = (const float*)d_in[23];
    const float* endv   = (const float*)d_in[24];
    float* out = (float*)d_out;

    char_lstm_kernel<<<NBT / WPB, 256>>>(char_tensor, char_lengths, char_emb,
                                         cWih_f, cWhh_f, cb_f, cWih_b, cWhh_b, cb_b);
    build_x_kernel<<<(NBT * NDW + 255) / 256, 256>>>(tok, recover, word_emb);
    sgemm_kernel<<<dim3(7, NBT / BM, 2), 256>>>(wWih_f, wb_f, wWih_b, wb_b);
    word_lstm_kernel<<<dim3(NB, 2), 400>>>(wWhh_f, wWhh_b);
    emissions_kernel<<<NBT / 32, 256>>>(W_tag, b_tag);
    crf_kernel<<<NB, 32>>>(tag, trans, startv, endv);
    final_reduce<<<1, 32>>>(out);
}

// round 16
// speedup vs baseline: 1.2342x; 1.0936x over previous
#include <cuda_runtime.h>
#include <math.h>

// Problem constants
#define NB   64        // batch
#define NT   256       // seq len
#define NBT  16384     // NB*NT
#define NTC  16        // char seq len
#define NCE  25        // char embed
#define NCH  25        // char hidden
#define NWE  100       // word embed
#define NWH  100       // word hidden
#define NDW  150       // word-LSTM input dim
#define NL   25        // labels

typedef unsigned long long u64;

// Scratch (device globals; no allocations allowed)
__device__ float g_char_feat[NBT * 50];
__device__ float g_x[NBT * NDW];
__device__ float g_xw_f[NBT * 400];
__device__ float g_xw_b[NBT * 400];
__device__ float g_seq[NBT * 200];
__device__ float g_em[NBT * NL];
__device__ float g_crf[NB];

// FAST activations (MUFU-based, ~5 instr vs ~20 accurate). Per-step rel error
// ~1e-6; through 256 contractive LSTM steps stays ~1e-5 << 1e-3 budget
// (measured rel_err was 0.0 with accurate versions — huge headroom).
__device__ __forceinline__ float sigm(float x) {
    return __fdividef(1.f, 1.f + __expf(-x));
}
__device__ __forceinline__ float tanh_f(float x) {
    return 2.f * __fdividef(1.f, 1.f + __expf(-2.f * x)) - 1.f;
}

// ---- packed fp32x2 helpers (sm_103a): two EXACT fp32 FMAs per instruction ----
__device__ __forceinline__ u64 pack2(float lo, float hi) {
    u64 r; asm("mov.b64 %0, {%1, %2};" : "=l"(r) : "f"(lo), "f"(hi)); return r;
}
__device__ __forceinline__ void unpack2(u64 v, float& lo, float& hi) {
    asm("mov.b64 {%0, %1}, %2;" : "=f"(lo), "=f"(hi) : "l"(v));
}
__device__ __forceinline__ void ffma2(u64& d, u64 a, u64 b) {
    asm("fma.rn.f32x2 %0, %1, %2, %0;" : "+l"(d) : "l"(a), "l"(b));
}

// ---------------------------------------------------------------------------
// K1: char BiLSTM. 8 words per block (weights in regs, reused). Activations
// applied by EACH gate thread in the wide phase.
// ---------------------------------------------------------------------------
#define WPB 8

__global__ void char_lstm_kernel(const int* __restrict__ char_tensor,
                                 const int* __restrict__ char_lengths,
                                 const float* __restrict__ char_emb,
                                 const float* __restrict__ wih_f, const float* __restrict__ whh_f,
                                 const float* __restrict__ b_f,
                                 const float* __restrict__ wih_b, const float* __restrict__ whh_b,
                                 const float* __restrict__ b_b)
{
    int tid = threadIdx.x;
    int dir = tid >> 7;       // 0 fwd, 1 bwd
    int g = tid & 127;        // gate id (valid < 100)

    __shared__ float ce_s[NTC][NCE];
    __shared__ int cidx[NTC];
    __shared__ float h_s[2][NCH];
    __shared__ float gate_s[2][100];

    // Load weights once; reuse for all WPB words.
    float wih_r[NCE], whh_r[NCH], br = 0.f;
    if (g < 100) {
        const float* wih = dir ? wih_b : wih_f;
        const float* whh = dir ? whh_b : whh_f;
        br = (dir ? b_b : b_f)[g];
#pragma unroll
        for (int k = 0; k < NCE; k++) wih_r[k] = wih[k * 100 + g];
#pragma unroll
        for (int k = 0; k < NCH; k++) whh_r[k] = whh[k * 100 + g];
    }
    int gtype = g / 25;       // 0:i 1:f 2:g 3:o

    for (int w = 0; w < WPB; w++) {
        int word = blockIdx.x * WPB + w;
        int len = char_lengths[word];

        if (tid < NTC) cidx[tid] = char_tensor[word * NTC + tid];
        __syncthreads();
        for (int e = tid; e < NTC * NCE; e += 256) {
            int t = e / NCE, k = e % NCE;
            ce_s[t][k] = char_emb[cidx[t] * NCE + k];
        }

        float c = 0.f;
        if (g < NCH) h_s[dir][g] = 0.f;
        __syncthreads();

        for (int t = 0; t < len; t++) {
            int xt = dir ? (len - 1 - t) : t;
            if (g < 100) {
                float a0 = br, a1 = 0.f, a2 = 0.f, a3 = 0.f;
#pragma unroll
                for (int k = 0; k < 24; k += 4) {
                    a0 += ce_s[xt][k + 0] * wih_r[k + 0];
                    a1 += ce_s[xt][k + 1] * wih_r[k + 1];
                    a2 += ce_s[xt][k + 2] * wih_r[k + 2];
                    a3 += ce_s[xt][k + 3] * wih_r[k + 3];
                }
                a0 += ce_s[xt][24] * wih_r[24];
#pragma unroll
                for (int k = 0; k < 24; k += 4) {
                    a0 += h_s[dir][k + 0] * whh_r[k + 0];
                    a1 += h_s[dir][k + 1] * whh_r[k + 1];
                    a2 += h_s[dir][k + 2] * whh_r[k + 2];
                    a3 += h_s[dir][k + 3] * whh_r[k + 3];
                }
                a1 += h_s[dir][24] * whh_r[24];
                float raw = (a0 + a1) + (a2 + a3);
                gate_s[dir][g] = (gtype == 2) ? tanh_f(raw) : sigm(raw);
            }
            __syncthreads();
            if (g < NCH) {
                float i_ = gate_s[dir][g];
                float f_ = gate_s[dir][25 + g];
                float gg = gate_s[dir][50 + g];
                float o_ = gate_s[dir][75 + g];
                c = f_ * c + i_ * gg;
                h_s[dir][g] = o_ * tanh_f(c);
            }
            __syncthreads();
        }

        if (g < NCH) g_char_feat[word * 50 + dir * NCH + g] = h_s[dir][g];
        __syncthreads();  // protect ce_s/cidx/h_s before next word overwrites
    }
}

// ---------------------------------------------------------------------------
// K2: x = concat(word_emb[tok], char_feat[recover])
// ---------------------------------------------------------------------------
__global__ void build_x_kernel(const int* __restrict__ tok,
                               const int* __restrict__ recover,
                               const float* __restrict__ word_emb)
{
    int e = blockIdx.x * blockDim.x + threadIdx.x;
    if (e >= NBT * NDW) return;
    int r = e / NDW, c = e % NDW;
    float v;
    if (c < NWE) v = word_emb[(long long)tok[r] * NWE + c];
    else         v = g_char_feat[recover[r] * 50 + (c - NWE)];
    g_x[e] = v;
}

// ---------------------------------------------------------------------------
// K3: SGEMM  C[16384,400] = g_x[16384,150] @ W[150,400] + bias, both dirs via z.
// Tile 128x64, BK=16, 256 threads, 8 rows x 4 cols per thread, f32x2 mainloop.
// ---------------------------------------------------------------------------
#define BM 128
#define BN 64
#define BK 16

__global__ __launch_bounds__(256, 3)
void sgemm_kernel(const float* __restrict__ Wf, const float* __restrict__ bf,
                  const float* __restrict__ Wb, const float* __restrict__ bb)
{
    const int K = NDW, N = 400;
    const int which = blockIdx.z;
    const float* W    = which ? Wb : Wf;
    const float* bias = which ? bb : bf;
    float* C          = which ? g_xw_b : g_xw_f;

    __shared__ float As[BK][BM + 4];   // pad 4: 16B-aligned rows
    __shared__ u64   Bs2[BK][BN];      // {b,b} duplicated

    int tid = threadIdx.x;
    int tx = tid & 15;                 // 16 col-groups of 4
    int ty = tid >> 4;                 // 16 row-groups of 8
    int cbase = blockIdx.x * BN, rbase = blockIdx.y * BM;

    u64 acc[4][4];                     // [row-pair][col]
#pragma unroll
    for (int i = 0; i < 4; i++)
#pragma unroll
        for (int j = 0; j < 4; j++) acc[i][j] = 0ull;

    int ak = tid & 15, ar = tid >> 4;          // A: k fast (gmem-coalesced)
    int bc = tid & 63, bk = tid >> 6;          // B: c fast (gmem-coalesced)

    float aReg[8], bReg[4];
    const int NSTAGE = (K + BK - 1) / BK;      // 10

    // prefetch stage 0
    {
        int kk = 0;
#pragma unroll
        for (int l = 0; l < 8; l++) {
            int k = ak, r = ar + l * 16;
            aReg[l] = (kk + k < K) ? g_x[(rbase + r) * K + kk + k] : 0.f;
        }
#pragma unroll
        for (int l = 0; l < 4; l++) {
            int k = bk + l * 4, col = cbase + bc;
            bReg[l] = (kk + k < K && col < N) ? W[(kk + k) * N + col] : 0.f;
        }
    }

    for (int s = 0; s < NSTAGE; s++) {
#pragma unroll
        for (int l = 0; l < 8; l++) As[ak][ar + l * 16] = aReg[l];
#pragma unroll
        for (int l = 0; l < 4; l++) Bs2[bk + l * 4][bc] = pack2(bReg[l], bReg[l]);
        __syncthreads();

        if (s + 1 < NSTAGE) {
            int kk = (s + 1) * BK;
#pragma unroll
            for (int l = 0; l < 8; l++) {
                int k = ak, r = ar + l * 16;
                aReg[l] = (kk + k < K) ? g_x[(rbase + r) * K + kk + k] : 0.f;
            }
#pragma unroll
            for (int l = 0; l < 4; l++) {
                int k = bk + l * 4, col = cbase + bc;
                bReg[l] = (kk + k < K && col < N) ? W[(kk + k) * N + col] : 0.f;
            }
        }

#pragma unroll
        for (int k = 0; k < BK; k++) {
            const u64* ap = reinterpret_cast<const u64*>(&As[k][ty * 8]);
            u64 a0 = ap[0], a1 = ap[1], a2 = ap[2], a3 = ap[3];
            const u64* bp = &Bs2[k][tx * 4];
            u64 b0 = bp[0], b1 = bp[1], b2 = bp[2], b3 = bp[3];
            ffma2(acc[0][0], a0, b0); ffma2(acc[0][1], a0, b1);
            ffma2(acc[0][2], a0, b2); ffma2(acc[0][3], a0, b3);
            ffma2(acc[1][0], a1, b0); ffma2(acc[1][1], a1, b1);
            ffma2(acc[1][2], a1, b2); ffma2(acc[1][3], a1, b3);
            ffma2(acc[2][0], a2, b0); ffma2(acc[2][1], a2, b1);
            ffma2(acc[2][2], a2, b2); ffma2(acc[2][3], a2, b3);
            ffma2(acc[3][0], a3, b0); ffma2(acc[3][1], a3, b1);
            ffma2(acc[3][2], a3, b2); ffma2(acc[3][3], a3, b3);
        }
        __syncthreads();
    }

#pragma unroll
    for (int i = 0; i < 4; i++) {
        int row0 = rbase + ty * 8 + i * 2;
#pragma unroll
        for (int j = 0; j < 4; j++) {
            int col = cbase + tx * 4 + j;
            if (col < N) {
                float lo, hi;
                unpack2(acc[i][j], lo, hi);
                float bv = bias[col];
                C[row0 * N + col]       = lo + bv;
                C[(row0 + 1) * N + col] = hi + bv;
            }
        }
    }
}

// ---------------------------------------------------------------------------
// K4: word BiLSTM recurrence. One block per (seq, dir); 400 threads = gates.
// Wide-phase per-gate activations (now FAST), 4 independent ffma2 chains,
// xw prefetch. Narrow phase: c-update + one fast tanh.
// ---------------------------------------------------------------------------
__global__ __launch_bounds__(400, 1)
void word_lstm_kernel(const float* __restrict__ whh_f, const float* __restrict__ whh_b)
{
    int b = blockIdx.x;
    int dir = blockIdx.y;
    const float* whh = dir ? whh_b : whh_f;
    const float* xw = dir ? g_xw_b : g_xw_f;
    int g = threadIdx.x;  // 0..399
    int gtype = g / 100;  // 0:i 1:f 2:g 3:o

    u64 w2[NWH / 2];
#pragma unroll
    for (int k = 0; k < NWH; k += 2)
        w2[k >> 1] = pack2(whh[k * 400 + g], whh[(k + 1) * 400 + g]);

    __shared__ __align__(16) float h_s[NWH];
    __shared__ float gate_s[400];
    float c = 0.f;
    if (g < NWH) h_s[g] = 0.f;
    __syncthreads();

    const u64* hp = reinterpret_cast<const u64*>(h_s);

    long long idx0 = dir ? ((long long)(b * NT + NT - 1) * 400 + g)
                         : ((long long)(b * NT) * 400 + g);
    long long stride = dir ? -400 : 400;

    float x_cur = xw[idx0];

    for (int t = 0; t < NT; t++) {
        // prefetch next step's input (independent of everything below)
        float x_next = 0.f;
        if (t + 1 < NT) x_next = xw[idx0 + (long long)(t + 1) * stride];

        // 4 independent packed chains: depth 12-13 each
        u64 ac0 = 0ull, ac1 = 0ull, ac2 = 0ull, ac3 = 0ull;
#pragma unroll
        for (int k = 0; k < 48; k += 4) {
            ffma2(ac0, hp[k + 0], w2[k + 0]);
            ffma2(ac1, hp[k + 1], w2[k + 1]);
            ffma2(ac2, hp[k + 2], w2[k + 2]);
            ffma2(ac3, hp[k + 3], w2[k + 3]);
        }
        ffma2(ac0, hp[48], w2[48]);
        ffma2(ac1, hp[49], w2[49]);

        float p0, p1, p2, p3, p4, p5, p6, p7;
        unpack2(ac0, p0, p1);
        unpack2(ac1, p2, p3);
        unpack2(ac2, p4, p5);
        unpack2(ac3, p6, p7);
        float raw = x_cur + (((p0 + p1) + (p2 + p3)) + ((p4 + p5) + (p6 + p7)));
        // activation in the WIDE phase (fast MUFU forms)
        gate_s[g] = (gtype == 2) ? tanh_f(raw) : sigm(raw);
        __syncthreads();
        if (g < NWH) {
            float i_ = gate_s[g];
            float f_ = gate_s[100 + g];
            float gg = gate_s[200 + g];
            float o_ = gate_s[300 + g];
            c = f_ * c + i_ * gg;
            float hv = o_ * tanh_f(c);
            h_s[g] = hv;
            int tt = dir ? (NT - 1 - t) : t;
            g_seq[(b * NT + tt) * 200 + dir * NWH + g] = hv;
        }
        __syncthreads();
        x_cur = x_next;
    }
}

// ---------------------------------------------------------------------------
// K5: emissions em = seq @ W_tag + b_tag. Block handles 32 rows from smem.
// ---------------------------------------------------------------------------
__global__ void emissions_kernel(const float* __restrict__ Wt, const float* __restrict__ bt)
{
    __shared__ float wt_s[200 * NL];
    __shared__ float rows_s[32][200];
    int base_row = blockIdx.x * 32;
    for (int e = threadIdx.x; e < 200 * NL; e += 256) wt_s[e] = Wt[e];
    for (int e = threadIdx.x; e < 32 * 200; e += 256)
        rows_s[e / 200][e % 200] = g_seq[(base_row + e / 200) * 200 + e % 200];
    __syncthreads();
    for (int o = threadIdx.x; o < 32 * NL; o += 256) {
        int r = o / NL, l = o % NL;
        float acc = bt[l];
#pragma unroll 8
        for (int k = 0; k < 200; k++) acc += rows_s[r][k] * wt_s[k * NL + l];
        g_em[(base_row + r) * NL + l] = acc;
    }
}

// ---------------------------------------------------------------------------
// K6: CRF NLL per batch element. One warp per batch row.
// Per-step max and sum use PAIRWISE TREES (depth 5).
// ---------------------------------------------------------------------------
__device__ __forceinline__ float tree_max25(const float* v) {
    float r[NL];
#pragma unroll
    for (int i = 0; i < NL; i++) r[i] = v[i];
    int n = NL;
#pragma unroll
    while (n > 1) {
        int h = (n + 1) >> 1;
#pragma unroll
        for (int i = 0; i < n / 2; i++) r[i] = fmaxf(r[2 * i], r[2 * i + 1]);
        if (n & 1) r[n / 2] = r[n - 1];
        n = h;
    }
    return r[0];
}

__device__ __forceinline__ float tree_sum25(const float* v) {
    float r[NL];
#pragma unroll
    for (int i = 0; i < NL; i++) r[i] = v[i];
    int n = NL;
#pragma unroll
    while (n > 1) {
        int h = (n + 1) >> 1;
#pragma unroll
        for (int i = 0; i < n / 2; i++) r[i] = r[2 * i] + r[2 * i + 1];
        if (n & 1) r[n / 2] = r[n - 1];
        n = h;
    }
    return r[0];
}

__global__ void crf_kernel(const int* __restrict__ tags,
                           const float* __restrict__ trans,
                           const float* __restrict__ startv,
                           const float* __restrict__ endv)
{
    int b = blockIdx.x;
    int j = threadIdx.x;  // 0..31
    const float L2E = 1.4426950408889634f;

    // ---- gold path score ----
    float gold = 0.f;
    for (int t = j; t < NT; t += 32) {
        int tg = tags[b * NT + t];
        gold += g_em[(b * NT + t) * NL + tg];
        if (t < NT - 1) gold += trans[tg * NL + tags[b * NT + t + 1]];
    }
    if (j == 0) gold += startv[tags[b * NT]] + endv[tags[b * NT + NT - 1]];
#pragma unroll
    for (int o = 16; o > 0; o >>= 1) gold += __shfl_xor_sync(0xffffffffu, gold, o);

    // ---- forward algorithm ----
    float tr[NL];
#pragma unroll
    for (int i = 0; i < NL; i++) tr[i] = 0.f;
    if (j < NL) {
#pragma unroll
        for (int i = 0; i < NL; i++) tr[i] = trans[i * NL + j];
    }
    float a = (j < NL) ? (startv[j] + g_em[(b * NT) * NL + j]) : -1e30f;

    for (int t = 1; t < NT; t++) {
        float v[NL];
#pragma unroll
        for (int i = 0; i < NL; i++) {
            float ai = __shfl_sync(0xffffffffu, a, i);
            v[i] = ai + tr[i];
        }
        float m = tree_max25(v);
        float e[NL];
#pragma unroll
        for (int i = 0; i < NL; i++) e[i] = exp2f((v[i] - m) * L2E);
        float s = tree_sum25(e);
        float na = m + __logf(s) + ((j < NL) ? g_em[(b * NT + t) * NL + j] : 0.f);
        a = (j < NL) ? na : -1e30f;
    }

    float z = (j < NL) ? a + endv[j] : -1e30f;
    float m = z;
#pragma unroll
    for (int o = 16; o > 0; o >>= 1) m = fmaxf(m, __shfl_xor_sync(0xffffffffu, m, o));
    float s = exp2f((z - m) * L2E);
#pragma unroll
    for (int o = 16; o > 0; o >>= 1) s += __shfl_xor_sync(0xffffffffu, s, o);
    if (j == 0) g_crf[b] = (m + __logf(s)) - gold;
}

// ---------------------------------------------------------------------------
// K7: deterministic final reduction
// ---------------------------------------------------------------------------
__global__ void final_reduce(float* out)
{
    if (threadIdx.x == 0) {
        float s = 0.f;
        for (int b = 0; b < NB; b++) s += g_crf[b];
        out[0] = s;
    }
}

extern "C" void kernel_launch(void* const* d_in, const int* in_sizes, int n_in,
                              void* d_out, int out_size)
{
    const int* tok          = (const int*)d_in[0];
    const int* tag          = (const int*)d_in[1];
    // d_in[2] lengths: all T, unused
    const int* char_tensor  = (const int*)d_in[3];
    const int* char_lengths = (const int*)d_in[4];
    const int* recover      = (const int*)d_in[5];
    const float* word_emb   = (const float*)d_in[6];
    const float* char_emb   = (const float*)d_in[7];
    const float* cWih_f = (const float*)d_in[8];
    const float* cWhh_f = (const float*)d_in[9];
    const float* cb_f   = (const float*)d_in[10];
    const float* cWih_b = (const float*)d_in[11];
    const float* cWhh_b = (const float*)d_in[12];
    const float* cb_b   = (const float*)d_in[13];
    const float* wWih_f = (const float*)d_in[14];
    const float* wWhh_f = (const float*)d_in[15];
    const float* wb_f   = (const float*)d_in[16];
    const float* wWih_b = (const float*)d_in[17];
    const float* wWhh_b = (const float*)d_in[18];
    const float* wb_b   = (const float*)d_in[19];
    const float* W_tag  = (const float*)d_in[20];
    const float* b_tag  = (const float*)d_in[21];
    const float* trans  = (const float*)d_in[22];
    const float* startv = (const float*)d_in[23];
    const float* endv   = (const float*)d_in[24];
    float* out = (float*)d_out;

    char_lstm_kernel<<<NBT / WPB, 256>>>(char_tensor, char_lengths, char_emb,
                                         cWih_f, cWhh_f, cb_f, cWih_b, cWhh_b, cb_b);
    build_x_kernel<<<(NBT * NDW + 255) / 256, 256>>>(tok, recover, word_emb);
    sgemm_kernel<<<dim3(7, NBT / BM, 2), 256>>>(wWih_f, wb_f, wWih_b, wb_b);
    word_lstm_kernel<<<dim3(NB, 2), 400>>>(wWhh_f, wWhh_b);
    emissions_kernel<<<NBT / 32, 256>>>(W_tag, b_tag);
    crf_kernel<<<NB, 32>>>(tag, trans, startv, endv);
    final_reduce<<<1, 32>>>(out);
}